// round 1
// baseline (speedup 1.0000x reference)
#include <cuda_runtime.h>
#include <cuda_bf16.h>

// Problem constants (fixed by reference)
#define N_NODES 50000
#define R_REL   32
#define DDIM    128
#define E_EDGES 600000
#define T_TRIP  8192

#define BLK_E   64                               // edge rows per GEMM tile
#define MAX_TILES (E_EDGES / BLK_E + R_REL)      // 9407 upper bound
#define XP      68                               // padded Xs row (bank-conflict + 16B align)

// -------- device scratch (static, no allocation) --------
__device__ int   g_is64;
__device__ int   g_cnt[N_NODES * R_REL];   // per (tgt,rel) edge count
__device__ float g_h[(size_t)N_NODES * DDIM];
__device__ int   g_src[E_EDGES];
__device__ int   g_tgt[E_EDGES];
__device__ int   g_rel[E_EDGES];
__device__ int   g_perm[E_EDGES];
__device__ int   g_head[T_TRIP], g_tail[T_TRIP], g_ridx[T_TRIP];
__device__ int   g_hist[R_REL];
__device__ int   g_off[R_REL + 1];
__device__ int   g_cursor[R_REL];
__device__ int   g_tile_rel[MAX_TILES];
__device__ int   g_tile_start[MAX_TILES];
__device__ int   g_ntiles;

// -------- helpers --------
__device__ __forceinline__ int ld_idx(const void* p, long long i, int is64) {
    return is64 ? (int)((const long long*)p)[i] : ((const int*)p)[i];
}

// -------- K1: zero the (tgt,rel) counter --------
__global__ void zero_cnt_kernel() {
    int i = blockIdx.x * blockDim.x + threadIdx.x;
    if (i < N_NODES * R_REL) g_cnt[i] = 0;
}

// -------- K2: dtype detect + zero small state --------
__global__ void init_kernel(const void* edge_index) {
    int tid = threadIdx.x;
    if (tid < R_REL) g_hist[tid] = 0;
    if (tid == 0) {
        // int64 little-endian with values < 2^31 has zero high words; int32 data
        // would place real (almost surely nonzero) indices at odd 32-bit slots.
        const unsigned int* p = (const unsigned int*)edge_index;
        int is64 = 1;
        for (int k = 0; k < 64; ++k) {
            if (p[2 * k + 1] != 0u) { is64 = 0; break; }
        }
        g_is64 = is64;
    }
}

// -------- K3: convert edges to int32 + histograms --------
__global__ void convert_edges_kernel(const void* edge_index, const void* edge_type) {
    int e = blockIdx.x * blockDim.x + threadIdx.x;
    if (e >= E_EDGES) return;
    int is64 = g_is64;
    int s = ld_idx(edge_index, e, is64);
    int t = ld_idx(edge_index, (long long)E_EDGES + e, is64);
    int r = ld_idx(edge_type, e, is64);
    g_src[e] = s;
    g_tgt[e] = t;
    g_rel[e] = r;
    atomicAdd(&g_cnt[t * R_REL + r], 1);
    atomicAdd(&g_hist[r], 1);
}

// -------- K4: convert triplets --------
__global__ void convert_trip_kernel(const void* head, const void* tail, const void* ridx) {
    int i = blockIdx.x * blockDim.x + threadIdx.x;
    if (i >= T_TRIP) return;
    int is64 = g_is64;
    g_head[i] = ld_idx(head, i, is64);
    g_tail[i] = ld_idx(tail, i, is64);
    g_ridx[i] = ld_idx(ridx, i, is64);
}

// -------- K5: prefix sums + tile descriptors --------
__global__ void scan_kernel() {
    __shared__ int off[R_REL + 1], toff[R_REL + 1];
    int tid = threadIdx.x;
    if (tid == 0) {
        int acc = 0, tacc = 0;
        for (int r = 0; r < R_REL; ++r) {
            off[r] = acc; toff[r] = tacc;
            int c = g_hist[r];
            acc += c;
            tacc += (c + BLK_E - 1) / BLK_E;
        }
        off[R_REL] = acc; toff[R_REL] = tacc;
        g_ntiles = tacc;
        g_off[R_REL] = acc;
    }
    __syncthreads();
    if (tid < R_REL) {
        g_off[tid] = off[tid];
        g_cursor[tid] = off[tid];
        int c = g_hist[tid];
        int nt = (c + BLK_E - 1) / BLK_E;
        int tb = toff[tid];
        for (int i = 0; i < nt; ++i) {
            g_tile_rel[tb + i] = tid;
            g_tile_start[tb + i] = off[tid] + i * BLK_E;
        }
    }
}

// -------- K6: scatter edges into relation-sorted order --------
__global__ void scatter_kernel() {
    int e = blockIdx.x * blockDim.x + threadIdx.x;
    if (e >= E_EDGES) return;
    int r = g_rel[e];
    int pos = atomicAdd(&g_cursor[r], 1);
    g_perm[pos] = e;
}

// -------- K7: h = x @ W_root + bias (64-node tiles) --------
__global__ void __launch_bounds__(256, 2)
root_gemm_kernel(const float* __restrict__ x, const float* __restrict__ Wroot,
                 const float* __restrict__ bias) {
    extern __shared__ float sm[];
    float* Ws = sm;                 // [128][128]
    float* Xs = sm + DDIM * DDIM;   // [128][XP] transposed: Xs[k][row]

    int tid = threadIdx.x;
    int n0 = blockIdx.x * BLK_E;
    int rows = min(BLK_E, N_NODES - n0);

    // load W_root
    const float4* Wg = (const float4*)Wroot;
    float4* Ws4 = (float4*)Ws;
    #pragma unroll
    for (int i = 0; i < 16; ++i) Ws4[tid + i * 256] = Wg[tid + i * 256];
    __syncthreads();

    // gather x tile (transposed into Xs)
    for (int idx = tid; idx < BLK_E * DDIM; idx += 256) {
        int row = idx >> 7, k = idx & 127;
        float v = 0.0f;
        if (row < rows) v = x[(size_t)(n0 + row) * DDIM + k];
        Xs[k * XP + row] = v;
    }
    __syncthreads();

    int tx = tid & 15, ty = tid >> 4;
    int c0 = tx * 8, r0 = ty * 4;
    float acc[4][8];
    #pragma unroll
    for (int i = 0; i < 4; ++i)
        #pragma unroll
        for (int j = 0; j < 8; ++j) acc[i][j] = 0.0f;

    #pragma unroll 4
    for (int k = 0; k < DDIM; ++k) {
        float4 a  = *(const float4*)&Xs[k * XP + r0];
        float4 b0 = *(const float4*)&Ws[k * DDIM + c0];
        float4 b1 = *(const float4*)&Ws[k * DDIM + c0 + 4];
        float av[4] = {a.x, a.y, a.z, a.w};
        float bv[8] = {b0.x, b0.y, b0.z, b0.w, b1.x, b1.y, b1.z, b1.w};
        #pragma unroll
        for (int i = 0; i < 4; ++i)
            #pragma unroll
            for (int j = 0; j < 8; ++j) acc[i][j] += av[i] * bv[j];
    }

    float bv[8];
    #pragma unroll
    for (int j = 0; j < 8; ++j) bv[j] = bias[c0 + j];
    #pragma unroll
    for (int i = 0; i < 4; ++i) {
        int row = r0 + i;
        if (row < rows) {
            float* hp = g_h + (size_t)(n0 + row) * DDIM + c0;
            #pragma unroll
            for (int j = 0; j < 8; ++j) hp[j] = acc[i][j] + bv[j];
        }
    }
}

// -------- K8: per-relation grouped edge GEMM, atomic scatter-add into h --------
__global__ void __launch_bounds__(256, 2)
edge_gemm_kernel(const float* __restrict__ x, const float* __restrict__ W) {
    int b = blockIdx.x;
    if (b >= g_ntiles) return;
    int r = g_tile_rel[b];
    int start = g_tile_start[b];
    int cntE = min(BLK_E, g_off[r + 1] - start);

    extern __shared__ float sm[];
    float* Ws = sm;                 // [128][128] = W_r
    float* Xs = sm + DDIM * DDIM;   // [128][XP]
    __shared__ int   s_s[BLK_E];
    __shared__ int   s_t[BLK_E];
    __shared__ float s_norm[BLK_E];

    int tid = threadIdx.x;
    if (tid < BLK_E) {
        if (tid < cntE) {
            int e = g_perm[start + tid];
            int s = g_src[e], t = g_tgt[e];
            s_s[tid] = s;
            s_t[tid] = t;
            s_norm[tid] = 1.0f / (float)g_cnt[t * R_REL + r];
        } else {
            s_s[tid] = 0; s_t[tid] = -1; s_norm[tid] = 0.0f;
        }
    }

    // load W_r
    const float4* Wg = (const float4*)(W + (size_t)r * DDIM * DDIM);
    float4* Ws4 = (float4*)Ws;
    #pragma unroll
    for (int i = 0; i < 16; ++i) Ws4[tid + i * 256] = Wg[tid + i * 256];
    __syncthreads();

    // gather scaled x[src] rows (transposed into Xs)
    for (int idx = tid; idx < BLK_E * DDIM; idx += 256) {
        int row = idx >> 7, k = idx & 127;
        float v = 0.0f;
        if (row < cntE) v = x[(size_t)s_s[row] * DDIM + k] * s_norm[row];
        Xs[k * XP + row] = v;
    }
    __syncthreads();

    int tx = tid & 15, ty = tid >> 4;
    int c0 = tx * 8, r0 = ty * 4;
    float acc[4][8];
    #pragma unroll
    for (int i = 0; i < 4; ++i)
        #pragma unroll
        for (int j = 0; j < 8; ++j) acc[i][j] = 0.0f;

    #pragma unroll 4
    for (int k = 0; k < DDIM; ++k) {
        float4 a  = *(const float4*)&Xs[k * XP + r0];
        float4 b0 = *(const float4*)&Ws[k * DDIM + c0];
        float4 b1 = *(const float4*)&Ws[k * DDIM + c0 + 4];
        float av[4] = {a.x, a.y, a.z, a.w};
        float bv[8] = {b0.x, b0.y, b0.z, b0.w, b1.x, b1.y, b1.z, b1.w};
        #pragma unroll
        for (int i = 0; i < 4; ++i)
            #pragma unroll
            for (int j = 0; j < 8; ++j) acc[i][j] += av[i] * bv[j];
    }

    #pragma unroll
    for (int i = 0; i < 4; ++i) {
        int row = r0 + i;
        if (row < cntE) {
            float* hp = g_h + (size_t)s_t[row] * DDIM + c0;
            #pragma unroll
            for (int j = 0; j < 8; ++j) atomicAdd(hp + j, acc[i][j]);
        }
    }
}

// -------- K9: fused relu + DistMult scoring (1 warp / triplet) --------
__global__ void score_kernel(const float* __restrict__ rel_emb, float* __restrict__ out) {
    int gt = blockIdx.x * blockDim.x + threadIdx.x;
    int tri = gt >> 5;
    int lane = gt & 31;
    if (tri >= T_TRIP) return;
    int hn = g_head[tri], tn = g_tail[tri], r = g_ridx[tri];
    const float4 a = *(const float4*)&g_h[(size_t)hn * DDIM + lane * 4];
    const float4 b = *(const float4*)&g_h[(size_t)tn * DDIM + lane * 4];
    const float4 c = *(const float4*)&rel_emb[(size_t)r * DDIM + lane * 4];
    float s = fmaxf(a.x, 0.0f) * c.x * fmaxf(b.x, 0.0f)
            + fmaxf(a.y, 0.0f) * c.y * fmaxf(b.y, 0.0f)
            + fmaxf(a.z, 0.0f) * c.z * fmaxf(b.z, 0.0f)
            + fmaxf(a.w, 0.0f) * c.w * fmaxf(b.w, 0.0f);
    #pragma unroll
    for (int o = 16; o > 0; o >>= 1) s += __shfl_down_sync(0xffffffffu, s, o);
    if (lane == 0) out[tri] = s;
}

// -------- launch --------
extern "C" void kernel_launch(void* const* d_in, const int* in_sizes, int n_in,
                              void* d_out, int out_size) {
    const float* x        = (const float*)d_in[0];
    const float* W        = (const float*)d_in[1];
    const float* Wroot    = (const float*)d_in[2];
    const float* bias     = (const float*)d_in[3];
    const float* rel_emb  = (const float*)d_in[4];
    const void*  edge_idx = d_in[5];
    const void*  edge_typ = d_in[6];
    const void*  head     = d_in[7];
    const void*  tail     = d_in[8];
    const void*  ridx     = d_in[9];
    float* out = (float*)d_out;

    const int SMEM = (DDIM * DDIM + DDIM * XP) * (int)sizeof(float); // 100352 B
    cudaFuncSetAttribute(root_gemm_kernel, cudaFuncAttributeMaxDynamicSharedMemorySize, SMEM);
    cudaFuncSetAttribute(edge_gemm_kernel, cudaFuncAttributeMaxDynamicSharedMemorySize, SMEM);

    zero_cnt_kernel<<<(N_NODES * R_REL + 255) / 256, 256>>>();
    init_kernel<<<1, 64>>>(edge_idx);
    convert_edges_kernel<<<(E_EDGES + 255) / 256, 256>>>(edge_idx, edge_typ);
    convert_trip_kernel<<<(T_TRIP + 255) / 256, 256>>>(head, tail, ridx);
    scan_kernel<<<1, 32>>>();
    scatter_kernel<<<(E_EDGES + 255) / 256, 256>>>();
    root_gemm_kernel<<<(N_NODES + BLK_E - 1) / BLK_E, 256, SMEM>>>(x, Wroot, bias);
    edge_gemm_kernel<<<MAX_TILES, 256, SMEM>>>(x, W);
    score_kernel<<<(T_TRIP * 32 + 255) / 256, 256>>>(rel_emb, out);
}

// round 3
// speedup vs baseline: 1.7042x; 1.7042x over previous
#include <cuda_runtime.h>
#include <cuda_bf16.h>
#include <cstdint>

// Problem constants (fixed by reference)
#define N_NODES 50000
#define R_REL   32
#define DDIM    128
#define E_EDGES 600000
#define T_TRIP  8192

#define BLK_E   128                                   // edge rows per MMA tile
#define MAX_TILES (E_EDGES / BLK_E + R_REL + 1)       // 4720 upper bound
#define XP      68                                    // root-gemm Xs padding

// smem byte offsets within extern dynamic smem (each region 32 KB)
#define SM_A_HI 0
#define SM_A_LO 32768
#define SM_B_HI 65536
#define SM_B_LO 98304
#define SMEM_EDGE_BYTES 131072

__device__ __forceinline__ uint32_t smem_to_u32(const void* smem_ptr) {
    uint32_t addr;
    asm("{ .reg .u64 tmp; cvta.to.shared.u64 tmp, %1; cvt.u32.u64 %0, tmp; }"
        : "=r"(addr) : "l"(smem_ptr));
    return addr;
}
// XOR swizzle: row-major [128][128] bf16, 256B/row, 16 chunks of 16B per row.
__device__ __forceinline__ uint32_t swz(uint32_t row, uint32_t chunk) {
    return row * 256u + ((chunk ^ (row & 7u)) << 4);
}
#define LDMX4(r, addr) \
    asm volatile("ldmatrix.sync.aligned.m8n8.x4.shared.b16 {%0,%1,%2,%3}, [%4];" \
        : "=r"((r)[0]), "=r"((r)[1]), "=r"((r)[2]), "=r"((r)[3]) : "r"(addr))
#define MMA_BF16(d, a, b0, b1) \
    asm volatile("mma.sync.aligned.m16n8k16.row.col.f32.bf16.bf16.f32 " \
        "{%0,%1,%2,%3}, {%4,%5,%6,%7}, {%8,%9}, {%0,%1,%2,%3};" \
        : "+f"((d)[0]), "+f"((d)[1]), "+f"((d)[2]), "+f"((d)[3]) \
        : "r"((a)[0]), "r"((a)[1]), "r"((a)[2]), "r"((a)[3]), "r"(b0), "r"(b1))

// -------- device scratch (static, no allocation) --------
__device__ int   g_is64;
__device__ int   g_cnt[N_NODES * R_REL];
__device__ float g_h[(size_t)N_NODES * DDIM];
__device__ int   g_src[E_EDGES];
__device__ int   g_tgt[E_EDGES];
__device__ int   g_rel[E_EDGES];
__device__ int   g_perm[E_EDGES];
__device__ int   g_head[T_TRIP], g_tail[T_TRIP], g_ridx[T_TRIP];
__device__ int   g_hist[R_REL];
__device__ int   g_off[R_REL + 1];
__device__ int   g_cursor[R_REL];
__device__ int   g_tile_rel[MAX_TILES];
__device__ int   g_tile_start[MAX_TILES];
__device__ int   g_ntiles;
// bf16 hi/lo splits
__device__ __align__(16) __nv_bfloat16 g_x_hi[(size_t)N_NODES * DDIM];
__device__ __align__(16) __nv_bfloat16 g_x_lo[(size_t)N_NODES * DDIM];
__device__ __align__(16) __nv_bfloat16 g_wt_hi[(size_t)R_REL * DDIM * DDIM]; // [r][out][in]
__device__ __align__(16) __nv_bfloat16 g_wt_lo[(size_t)R_REL * DDIM * DDIM];

__device__ __forceinline__ int ld_idx(const void* p, long long i, int is64) {
    return is64 ? (int)((const long long*)p)[i] : ((const int*)p)[i];
}

// -------- K1: zero per-(tgt,rel) counters --------
__global__ void zero_cnt_kernel() {
    int i = blockIdx.x * blockDim.x + threadIdx.x;
    if (i < N_NODES * R_REL) g_cnt[i] = 0;
}

// -------- K2: dtype detect + zero hist --------
__global__ void init_kernel(const void* edge_index) {
    int tid = threadIdx.x;
    if (tid < R_REL) g_hist[tid] = 0;
    if (tid == 0) {
        const unsigned int* p = (const unsigned int*)edge_index;
        int is64 = 1;
        for (int k = 0; k < 64; ++k)
            if (p[2 * k + 1] != 0u) { is64 = 0; break; }
        g_is64 = is64;
    }
}

// -------- K3: bf16 split of x --------
__global__ void split_x_kernel(const float* __restrict__ x) {
    int i = blockIdx.x * blockDim.x + threadIdx.x;
    if (i >= N_NODES * DDIM) return;
    float v = x[i];
    __nv_bfloat16 hi = __float2bfloat16(v);
    g_x_hi[i] = hi;
    g_x_lo[i] = __float2bfloat16(v - __bfloat162float(hi));
}

// -------- K4: transpose + bf16 split of W: Wt[r][o][i] = W[r][i][o] --------
__global__ void split_w_kernel(const float* __restrict__ W) {
    int idx = blockIdx.x * blockDim.x + threadIdx.x;
    if (idx >= R_REL * DDIM * DDIM) return;
    int r = idx >> 14;
    int o = (idx >> 7) & 127;
    int i = idx & 127;
    float v = W[(size_t)r * DDIM * DDIM + (size_t)i * DDIM + o];
    __nv_bfloat16 hi = __float2bfloat16(v);
    g_wt_hi[idx] = hi;
    g_wt_lo[idx] = __float2bfloat16(v - __bfloat162float(hi));
}

// -------- K5: convert edges + histograms --------
__global__ void convert_edges_kernel(const void* edge_index, const void* edge_type) {
    int e = blockIdx.x * blockDim.x + threadIdx.x;
    if (e >= E_EDGES) return;
    int is64 = g_is64;
    int s = ld_idx(edge_index, e, is64);
    int t = ld_idx(edge_index, (long long)E_EDGES + e, is64);
    int r = ld_idx(edge_type, e, is64);
    g_src[e] = s; g_tgt[e] = t; g_rel[e] = r;
    atomicAdd(&g_cnt[t * R_REL + r], 1);
    atomicAdd(&g_hist[r], 1);
}

// -------- K6: convert triplets --------
__global__ void convert_trip_kernel(const void* head, const void* tail, const void* ridx) {
    int i = blockIdx.x * blockDim.x + threadIdx.x;
    if (i >= T_TRIP) return;
    int is64 = g_is64;
    g_head[i] = ld_idx(head, i, is64);
    g_tail[i] = ld_idx(tail, i, is64);
    g_ridx[i] = ld_idx(ridx, i, is64);
}

// -------- K7: prefix sums + tile descriptors --------
__global__ void scan_kernel() {
    __shared__ int off[R_REL + 1], toff[R_REL + 1];
    int tid = threadIdx.x;
    if (tid == 0) {
        int acc = 0, tacc = 0;
        for (int r = 0; r < R_REL; ++r) {
            off[r] = acc; toff[r] = tacc;
            int c = g_hist[r];
            acc += c;
            tacc += (c + BLK_E - 1) / BLK_E;
        }
        off[R_REL] = acc; toff[R_REL] = tacc;
        g_ntiles = tacc;
        g_off[R_REL] = acc;
    }
    __syncthreads();
    if (tid < R_REL) {
        g_off[tid] = off[tid];
        g_cursor[tid] = off[tid];
        int c = g_hist[tid];
        int nt = (c + BLK_E - 1) / BLK_E;
        int tb = toff[tid];
        for (int i = 0; i < nt; ++i) {
            g_tile_rel[tb + i] = tid;
            g_tile_start[tb + i] = off[tid] + i * BLK_E;
        }
    }
}

// -------- K8: scatter edges into relation-sorted order --------
__global__ void scatter_kernel() {
    int e = blockIdx.x * blockDim.x + threadIdx.x;
    if (e >= E_EDGES) return;
    int r = g_rel[e];
    int pos = atomicAdd(&g_cursor[r], 1);
    g_perm[pos] = e;
}

// -------- K9: h = x @ W_root + bias (SIMT fp32, exact) --------
__global__ void __launch_bounds__(256, 2)
root_gemm_kernel(const float* __restrict__ x, const float* __restrict__ Wroot,
                 const float* __restrict__ bias) {
    extern __shared__ float sm[];
    float* Ws = sm;
    float* Xs = sm + DDIM * DDIM;
    int tid = threadIdx.x;
    int n0 = blockIdx.x * 64;
    int rows = min(64, N_NODES - n0);

    const float4* Wg = (const float4*)Wroot;
    float4* Ws4 = (float4*)Ws;
    #pragma unroll
    for (int i = 0; i < 16; ++i) Ws4[tid + i * 256] = Wg[tid + i * 256];
    __syncthreads();

    for (int idx = tid; idx < 64 * DDIM; idx += 256) {
        int row = idx >> 7, k = idx & 127;
        float v = 0.0f;
        if (row < rows) v = x[(size_t)(n0 + row) * DDIM + k];
        Xs[k * XP + row] = v;
    }
    __syncthreads();

    int tx = tid & 15, ty = tid >> 4;
    int c0 = tx * 8, r0 = ty * 4;
    float acc[4][8];
    #pragma unroll
    for (int i = 0; i < 4; ++i)
        #pragma unroll
        for (int j = 0; j < 8; ++j) acc[i][j] = 0.0f;

    #pragma unroll 4
    for (int k = 0; k < DDIM; ++k) {
        float4 a  = *(const float4*)&Xs[k * XP + r0];
        float4 b0 = *(const float4*)&Ws[k * DDIM + c0];
        float4 b1 = *(const float4*)&Ws[k * DDIM + c0 + 4];
        float av[4] = {a.x, a.y, a.z, a.w};
        float bv[8] = {b0.x, b0.y, b0.z, b0.w, b1.x, b1.y, b1.z, b1.w};
        #pragma unroll
        for (int i = 0; i < 4; ++i)
            #pragma unroll
            for (int j = 0; j < 8; ++j) acc[i][j] += av[i] * bv[j];
    }

    float bv[8];
    #pragma unroll
    for (int j = 0; j < 8; ++j) bv[j] = bias[c0 + j];
    #pragma unroll
    for (int i = 0; i < 4; ++i) {
        int row = r0 + i;
        if (row < rows) {
            float* hp = g_h + (size_t)(n0 + row) * DDIM + c0;
            #pragma unroll
            for (int j = 0; j < 8; ++j) hp[j] = acc[i][j] + bv[j];
        }
    }
}

// -------- K10: HMMA bf16x3 edge GEMM + vectorized scatter-add --------
__global__ void __launch_bounds__(256, 1)
edge_mma_kernel() {
    int b = blockIdx.x;
    if (b >= g_ntiles) return;

    extern __shared__ char smem[];
    __shared__ int   s_src[BLK_E];
    __shared__ int   s_tgt[BLK_E];
    __shared__ float s_norm[BLK_E];

    int tid  = threadIdx.x;
    int wid  = tid >> 5;
    int lane = tid & 31;
    uint32_t sbase = smem_to_u32(smem);

    int r = g_tile_rel[b];
    int start = g_tile_start[b];
    int cntE = min(BLK_E, g_off[r + 1] - start);

    // tile metadata (threads 0..127)
    if (tid < BLK_E) {
        if (tid < cntE) {
            int e = g_perm[start + tid];
            int s = g_src[e], t = g_tgt[e];
            s_src[tid] = s; s_tgt[tid] = t;
            s_norm[tid] = 1.0f / (float)g_cnt[t * R_REL + r];
        } else {
            s_src[tid] = 0; s_tgt[tid] = -1; s_norm[tid] = 0.0f;
        }
    }
    __syncthreads();

    // load B = W_r^T (hi+lo) and gather A = x[src] (hi+lo), XOR-swizzled.
    // 256 threads: each handles one (row, half) pair -> 8 uint4 chunks of 16B.
    {
        int row  = tid >> 1;
        int half = tid & 1;
        const uint4* bh = (const uint4*)(g_wt_hi + (size_t)r * DDIM * DDIM + row * DDIM + half * 64);
        const uint4* bl = (const uint4*)(g_wt_lo + (size_t)r * DDIM * DDIM + row * DDIM + half * 64);
        int node = s_src[row];
        const uint4* ah = (const uint4*)(g_x_hi + (size_t)node * DDIM + half * 64);
        const uint4* al = (const uint4*)(g_x_lo + (size_t)node * DDIM + half * 64);
        #pragma unroll
        for (int i = 0; i < 8; ++i) {
            uint32_t off = swz((uint32_t)row, (uint32_t)(half * 8 + i));
            *(uint4*)(smem + SM_B_HI + off) = bh[i];
            *(uint4*)(smem + SM_B_LO + off) = bl[i];
            *(uint4*)(smem + SM_A_HI + off) = ah[i];
            *(uint4*)(smem + SM_A_LO + off) = al[i];
        }
    }
    __syncthreads();

    // MMA mainloop: D = A_hi*B_hi + A_hi*B_lo + A_lo*B_hi
    int m0 = wid * 16;
    float acc[16][4];
    #pragma unroll
    for (int i = 0; i < 16; ++i)
        #pragma unroll
        for (int j = 0; j < 4; ++j) acc[i][j] = 0.0f;

    uint32_t lrow = (uint32_t)(lane & 15);
    uint32_t lchk = (uint32_t)(lane >> 4);

    #pragma unroll
    for (int ks = 0; ks < 8; ++ks) {
        uint32_t chunk = (uint32_t)(ks * 2) + lchk;
        uint32_t aoff = swz((uint32_t)m0 + lrow, chunk);
        uint32_t ah[4], al[4];
        LDMX4(ah, sbase + SM_A_HI + aoff);
        LDMX4(al, sbase + SM_A_LO + aoff);
        #pragma unroll
        for (int nt = 0; nt < 16; nt += 2) {
            uint32_t boff = swz((uint32_t)(nt * 8) + lrow, chunk);
            uint32_t bh[4], bl[4];
            LDMX4(bh, sbase + SM_B_HI + boff);
            LDMX4(bl, sbase + SM_B_LO + boff);
            MMA_BF16(acc[nt],     ah, bh[0], bh[2]);
            MMA_BF16(acc[nt],     ah, bl[0], bl[2]);
            MMA_BF16(acc[nt],     al, bh[0], bh[2]);
            MMA_BF16(acc[nt + 1], ah, bh[1], bh[3]);
            MMA_BF16(acc[nt + 1], ah, bl[1], bl[3]);
            MMA_BF16(acc[nt + 1], al, bh[1], bh[3]);
        }
    }

    // epilogue: scale by norm, red.v2 scatter-add into g_h
    {
        int r0 = m0 + (lane >> 2);
        int r1 = r0 + 8;
        int t0 = s_tgt[r0], t1 = s_tgt[r1];
        float f0 = s_norm[r0], f1 = s_norm[r1];
        float* h0 = g_h + (size_t)(t0 < 0 ? 0 : t0) * DDIM;
        float* h1 = g_h + (size_t)(t1 < 0 ? 0 : t1) * DDIM;
        int cb = (lane & 3) * 2;
        #pragma unroll
        for (int nt = 0; nt < 16; ++nt) {
            int col = nt * 8 + cb;
            if (t0 >= 0) {
                float v0 = acc[nt][0] * f0, v1 = acc[nt][1] * f0;
                asm volatile("red.global.add.v2.f32 [%0], {%1, %2};"
                             :: "l"(h0 + col), "f"(v0), "f"(v1) : "memory");
            }
            if (t1 >= 0) {
                float v2 = acc[nt][2] * f1, v3 = acc[nt][3] * f1;
                asm volatile("red.global.add.v2.f32 [%0], {%1, %2};"
                             :: "l"(h1 + col), "f"(v2), "f"(v3) : "memory");
            }
        }
    }
}

// -------- K11: fused relu + DistMult scoring --------
__global__ void score_kernel(const float* __restrict__ rel_emb, float* __restrict__ out) {
    int gt = blockIdx.x * blockDim.x + threadIdx.x;
    int tri = gt >> 5;
    int lane = gt & 31;
    if (tri >= T_TRIP) return;
    int hn = g_head[tri], tn = g_tail[tri], r = g_ridx[tri];
    const float4 a = *(const float4*)&g_h[(size_t)hn * DDIM + lane * 4];
    const float4 b = *(const float4*)&g_h[(size_t)tn * DDIM + lane * 4];
    const float4 c = *(const float4*)&rel_emb[(size_t)r * DDIM + lane * 4];
    float s = fmaxf(a.x, 0.0f) * c.x * fmaxf(b.x, 0.0f)
            + fmaxf(a.y, 0.0f) * c.y * fmaxf(b.y, 0.0f)
            + fmaxf(a.z, 0.0f) * c.z * fmaxf(b.z, 0.0f)
            + fmaxf(a.w, 0.0f) * c.w * fmaxf(b.w, 0.0f);
    #pragma unroll
    for (int o = 16; o > 0; o >>= 1) s += __shfl_down_sync(0xffffffffu, s, o);
    if (lane == 0) out[tri] = s;
}

// -------- launch --------
extern "C" void kernel_launch(void* const* d_in, const int* in_sizes, int n_in,
                              void* d_out, int out_size) {
    const float* x        = (const float*)d_in[0];
    const float* W        = (const float*)d_in[1];
    const float* Wroot    = (const float*)d_in[2];
    const float* bias     = (const float*)d_in[3];
    const float* rel_emb  = (const float*)d_in[4];
    const void*  edge_idx = d_in[5];
    const void*  edge_typ = d_in[6];
    const void*  head     = d_in[7];
    const void*  tail     = d_in[8];
    const void*  ridx     = d_in[9];
    float* out = (float*)d_out;

    const int SMEM_ROOT = (DDIM * DDIM + DDIM * XP) * (int)sizeof(float);
    cudaFuncSetAttribute(root_gemm_kernel, cudaFuncAttributeMaxDynamicSharedMemorySize, SMEM_ROOT);
    cudaFuncSetAttribute(edge_mma_kernel, cudaFuncAttributeMaxDynamicSharedMemorySize, SMEM_EDGE_BYTES);

    zero_cnt_kernel<<<(N_NODES * R_REL + 255) / 256, 256>>>();
    init_kernel<<<1, 64>>>(edge_idx);
    split_x_kernel<<<(N_NODES * DDIM + 255) / 256, 256>>>(x);
    split_w_kernel<<<(R_REL * DDIM * DDIM + 255) / 256, 256>>>(W);
    convert_edges_kernel<<<(E_EDGES + 255) / 256, 256>>>(edge_idx, edge_typ);
    convert_trip_kernel<<<(T_TRIP + 255) / 256, 256>>>(head, tail, ridx);
    scan_kernel<<<1, 32>>>();
    scatter_kernel<<<(E_EDGES + 255) / 256, 256>>>();
    root_gemm_kernel<<<(N_NODES + 63) / 64, 256, SMEM_ROOT>>>(x, Wroot, bias);
    edge_mma_kernel<<<MAX_TILES, 256, SMEM_EDGE_BYTES>>>();
    score_kernel<<<(T_TRIP * 32 + 255) / 256, 256>>>(rel_emb, out);
}

// round 4
// speedup vs baseline: 2.6443x; 1.5517x over previous
#include <cuda_runtime.h>
#include <cuda_bf16.h>
#include <cstdint>

// Problem constants (fixed by reference)
#define N_NODES 50000
#define R_REL   32
#define DDIM    128
#define E_EDGES 600000
#define T_TRIP  8192

#define BLK_E   128
#define MAX_TILES (E_EDGES / BLK_E + R_REL + 1)
#define XP      68
#define EDGE_GRID 148

// dynamic smem layout for edge kernel (192 KB)
#define SM_B_HI 0
#define SM_B_LO 32768
#define SM_A0   65536          // A buf 0: hi at +0, lo at +32768 (64 KB)
#define SM_A1   131072         // A buf 1
#define SMEM_EDGE_BYTES 196608

__device__ __forceinline__ uint32_t smem_to_u32(const void* smem_ptr) {
    uint32_t addr;
    asm("{ .reg .u64 tmp; cvta.to.shared.u64 tmp, %1; cvt.u32.u64 %0, tmp; }"
        : "=r"(addr) : "l"(smem_ptr));
    return addr;
}
// XOR swizzle: row-major [128][128] bf16, 256B/row, 16 chunks of 16B per row.
__device__ __forceinline__ uint32_t swz(uint32_t row, uint32_t chunk) {
    return row * 256u + ((chunk ^ (row & 7u)) << 4);
}
#define LDMX4(r, addr) \
    asm volatile("ldmatrix.sync.aligned.m8n8.x4.shared.b16 {%0,%1,%2,%3}, [%4];" \
        : "=r"((r)[0]), "=r"((r)[1]), "=r"((r)[2]), "=r"((r)[3]) : "r"(addr))
#define MMA_BF16(d, a, b0, b1) \
    asm volatile("mma.sync.aligned.m16n8k16.row.col.f32.bf16.bf16.f32 " \
        "{%0,%1,%2,%3}, {%4,%5,%6,%7}, {%8,%9}, {%0,%1,%2,%3};" \
        : "+f"((d)[0]), "+f"((d)[1]), "+f"((d)[2]), "+f"((d)[3]) \
        : "r"((a)[0]), "r"((a)[1]), "r"((a)[2]), "r"((a)[3]), "r"(b0), "r"(b1))
#define CP_ASYNC16(dst_u32, gptr) \
    asm volatile("cp.async.cg.shared.global [%0], [%1], 16;" \
        :: "r"(dst_u32), "l"(gptr) : "memory")
#define CP_COMMIT() asm volatile("cp.async.commit_group;" ::: "memory")
#define CP_WAIT0()  asm volatile("cp.async.wait_group 0;" ::: "memory")
#define CP_WAIT1()  asm volatile("cp.async.wait_group 1;" ::: "memory")

// -------- device scratch (static, no allocation) --------
__device__ int   g_is64;
__device__ int   g_cnt[N_NODES * R_REL];
__device__ float g_h[(size_t)N_NODES * DDIM];
__device__ int   g_src[E_EDGES];
__device__ int   g_tgt[E_EDGES];
__device__ int   g_rel[E_EDGES];
__device__ int   g_src_s[E_EDGES];      // relation-sorted
__device__ int   g_tgt_s[E_EDGES];
__device__ float g_norm_s[E_EDGES];
__device__ int   g_head[T_TRIP], g_tail[T_TRIP], g_ridx[T_TRIP];
__device__ int   g_hist[R_REL];
__device__ int   g_off[R_REL + 1];
__device__ int   g_cursor[R_REL];
__device__ int   g_tile_rel[MAX_TILES];
__device__ int   g_tile_start[MAX_TILES];
__device__ int   g_ntiles;
// bf16 hi/lo splits
__device__ __align__(16) __nv_bfloat16 g_x_hi[(size_t)N_NODES * DDIM];
__device__ __align__(16) __nv_bfloat16 g_x_lo[(size_t)N_NODES * DDIM];
__device__ __align__(16) __nv_bfloat16 g_wt_hi[(size_t)R_REL * DDIM * DDIM]; // [r][out][in]
__device__ __align__(16) __nv_bfloat16 g_wt_lo[(size_t)R_REL * DDIM * DDIM];

__device__ __forceinline__ int ld_idx(const void* p, long long i, int is64) {
    return is64 ? (int)((const long long*)p)[i] : ((const int*)p)[i];
}

// -------- K1: zero counters + dtype detect --------
__global__ void prep_kernel(const void* edge_index) {
    int i = blockIdx.x * blockDim.x + threadIdx.x;
    if (i < N_NODES * R_REL) g_cnt[i] = 0;
    if (blockIdx.x == 0) {
        if (threadIdx.x < R_REL) g_hist[threadIdx.x] = 0;
        if (threadIdx.x == 0) {
            const unsigned int* p = (const unsigned int*)edge_index;
            int is64 = 1;
            for (int k = 0; k < 64; ++k)
                if (p[2 * k + 1] != 0u) { is64 = 0; break; }
            g_is64 = is64;
        }
    }
}

// -------- K2: convert edges + triplets, warp-aggregated hist --------
__global__ void convert_kernel(const void* edge_index, const void* edge_type,
                               const void* head, const void* tail, const void* ridx) {
    int i = blockIdx.x * blockDim.x + threadIdx.x;
    int is64 = g_is64;
    if (i < T_TRIP) {
        g_head[i] = ld_idx(head, i, is64);
        g_tail[i] = ld_idx(tail, i, is64);
        g_ridx[i] = ld_idx(ridx, i, is64);
    }
    if (i >= E_EDGES) return;
    int s = ld_idx(edge_index, i, is64);
    int t = ld_idx(edge_index, (long long)E_EDGES + i, is64);
    int r = ld_idx(edge_type, i, is64);
    g_src[i] = s; g_tgt[i] = t; g_rel[i] = r;
    atomicAdd(&g_cnt[t * R_REL + r], 1);
    // warp-aggregated hist add
    unsigned am = __activemask();
    unsigned mask = __match_any_sync(am, r);
    int lane = threadIdx.x & 31;
    int leader = __ffs(mask) - 1;
    if (lane == leader) atomicAdd(&g_hist[r], __popc(mask));
}

// -------- K3: prefix sums + tile descriptors --------
__global__ void scan_kernel() {
    __shared__ int off[R_REL + 1], toff[R_REL + 1];
    int tid = threadIdx.x;
    if (tid == 0) {
        int acc = 0, tacc = 0;
        for (int r = 0; r < R_REL; ++r) {
            off[r] = acc; toff[r] = tacc;
            int c = g_hist[r];
            acc += c;
            tacc += (c + BLK_E - 1) / BLK_E;
        }
        off[R_REL] = acc; toff[R_REL] = tacc;
        g_ntiles = tacc;
        g_off[R_REL] = acc;
    }
    __syncthreads();
    if (tid < R_REL) {
        g_off[tid] = off[tid];
        g_cursor[tid] = off[tid];
        int c = g_hist[tid];
        int nt = (c + BLK_E - 1) / BLK_E;
        int tb = toff[tid];
        for (int i = 0; i < nt; ++i) {
            g_tile_rel[tb + i] = tid;
            g_tile_start[tb + i] = off[tid] + i * BLK_E;
        }
    }
}

// -------- K4: scatter into relation-sorted arrays (warp-aggregated cursor) --------
__global__ void scatter_kernel() {
    int e = blockIdx.x * blockDim.x + threadIdx.x;
    if (e >= E_EDGES) return;
    int r = g_rel[e];
    unsigned am = __activemask();
    unsigned mask = __match_any_sync(am, r);
    int lane = threadIdx.x & 31;
    int leader = __ffs(mask) - 1;
    int rank = __popc(mask & ((1u << lane) - 1u));
    int base;
    if (lane == leader) base = atomicAdd(&g_cursor[r], __popc(mask));
    base = __shfl_sync(mask, base, leader);
    int pos = base + rank;
    int t = g_tgt[e];
    g_src_s[pos] = g_src[e];
    g_tgt_s[pos] = t;
    g_norm_s[pos] = 1.0f / (float)g_cnt[t * R_REL + r];
}

// -------- K5: bf16 splits of x and W^T (fused) --------
#define XN (N_NODES * DDIM)
#define WN (R_REL * DDIM * DDIM)
__global__ void split_kernel(const float* __restrict__ x, const float* __restrict__ W) {
    int i = blockIdx.x * blockDim.x + threadIdx.x;
    if (i < XN) {
        float v = x[i];
        __nv_bfloat16 hi = __float2bfloat16(v);
        g_x_hi[i] = hi;
        g_x_lo[i] = __float2bfloat16(v - __bfloat162float(hi));
    }
    int j = i - XN;
    if (j >= 0 && j < WN) {
        int r = j >> 14;
        int o = (j >> 7) & 127;
        int k = j & 127;
        float v = W[(size_t)r * DDIM * DDIM + (size_t)k * DDIM + o];
        __nv_bfloat16 hi = __float2bfloat16(v);
        g_wt_hi[j] = hi;
        g_wt_lo[j] = __float2bfloat16(v - __bfloat162float(hi));
    }
}

// -------- K6: h = x @ W_root + bias (SIMT fp32, exact) --------
__global__ void __launch_bounds__(256, 2)
root_gemm_kernel(const float* __restrict__ x, const float* __restrict__ Wroot,
                 const float* __restrict__ bias) {
    extern __shared__ float sm[];
    float* Ws = sm;
    float* Xs = sm + DDIM * DDIM;
    int tid = threadIdx.x;
    int n0 = blockIdx.x * 64;
    int rows = min(64, N_NODES - n0);

    const float4* Wg = (const float4*)Wroot;
    float4* Ws4 = (float4*)Ws;
    #pragma unroll
    for (int i = 0; i < 16; ++i) Ws4[tid + i * 256] = Wg[tid + i * 256];
    __syncthreads();

    for (int idx = tid; idx < 64 * DDIM; idx += 256) {
        int row = idx >> 7, k = idx & 127;
        float v = 0.0f;
        if (row < rows) v = x[(size_t)(n0 + row) * DDIM + k];
        Xs[k * XP + row] = v;
    }
    __syncthreads();

    int tx = tid & 15, ty = tid >> 4;
    int c0 = tx * 8, r0 = ty * 4;
    float acc[4][8];
    #pragma unroll
    for (int i = 0; i < 4; ++i)
        #pragma unroll
        for (int j = 0; j < 8; ++j) acc[i][j] = 0.0f;

    #pragma unroll 4
    for (int k = 0; k < DDIM; ++k) {
        float4 a  = *(const float4*)&Xs[k * XP + r0];
        float4 b0 = *(const float4*)&Ws[k * DDIM + c0];
        float4 b1 = *(const float4*)&Ws[k * DDIM + c0 + 4];
        float av[4] = {a.x, a.y, a.z, a.w};
        float bv[8] = {b0.x, b0.y, b0.z, b0.w, b1.x, b1.y, b1.z, b1.w};
        #pragma unroll
        for (int i = 0; i < 4; ++i)
            #pragma unroll
            for (int j = 0; j < 8; ++j) acc[i][j] += av[i] * bv[j];
    }

    float bv[8];
    #pragma unroll
    for (int j = 0; j < 8; ++j) bv[j] = bias[c0 + j];
    #pragma unroll
    for (int i = 0; i < 4; ++i) {
        int row = r0 + i;
        if (row < rows) {
            float* hp = g_h + (size_t)(n0 + row) * DDIM + c0;
            #pragma unroll
            for (int j = 0; j < 8; ++j) hp[j] = acc[i][j] + bv[j];
        }
    }
}

// -------- K7: persistent HMMA bf16x3 edge GEMM, cp.async double-buffered --------
__global__ void __launch_bounds__(256, 1)
edge_mma_kernel() {
    extern __shared__ char smem[];
    __shared__ int   s_tgt[2][BLK_E];
    __shared__ float s_norm[2][BLK_E];

    int ntiles = g_ntiles;
    int per = (ntiles + EDGE_GRID - 1) / EDGE_GRID;
    int t0 = blockIdx.x * per;
    int t1 = min(ntiles, t0 + per);
    if (t0 >= t1) return;

    int tid  = threadIdx.x;
    int wid  = tid >> 5;
    int lane = tid & 31;
    uint32_t sbase = smem_to_u32(smem);
    int lrow_half = tid >> 1;      // 0..127 (row for loads)
    int lhalf = tid & 1;           // 0/1 (64-col half)

    // ---- prologue: meta + A prefetch for tile t0 into buf 0 ----
    {
        int r = g_tile_rel[t0];
        int start = g_tile_start[t0];
        int cntE = min(BLK_E, g_off[r + 1] - start);
        if (tid < BLK_E) {
            if (tid < cntE) {
                s_tgt[0][tid] = g_tgt_s[start + tid];
                s_norm[0][tid] = g_norm_s[start + tid];
            } else {
                s_tgt[0][tid] = -1; s_norm[0][tid] = 0.0f;
            }
        }
        int node = (lrow_half < cntE) ? g_src_s[start + lrow_half] : 0;
        const __nv_bfloat16* ah = g_x_hi + (size_t)node * DDIM + lhalf * 64;
        const __nv_bfloat16* al = g_x_lo + (size_t)node * DDIM + lhalf * 64;
        uint32_t ab = sbase + SM_A0;
        #pragma unroll
        for (int i = 0; i < 8; ++i) {
            uint32_t off = swz((uint32_t)lrow_half, (uint32_t)(lhalf * 8 + i));
            CP_ASYNC16(ab + off, ah + i * 8);
            CP_ASYNC16(ab + 32768u + off, al + i * 8);
        }
        CP_COMMIT();
    }

    int prev_rel = -1;

    for (int t = t0; t < t1; ++t) {
        int cur = (t - t0) & 1;
        int nxt = cur ^ 1;
        int r = g_tile_rel[t];

        // ---- prefetch meta + A for tile t+1 ----
        if (t + 1 < t1) {
            int rn = g_tile_rel[t + 1];
            int startn = g_tile_start[t + 1];
            int cntN = min(BLK_E, g_off[rn + 1] - startn);
            if (tid < BLK_E) {
                if (tid < cntN) {
                    s_tgt[nxt][tid] = g_tgt_s[startn + tid];
                    s_norm[nxt][tid] = g_norm_s[startn + tid];
                } else {
                    s_tgt[nxt][tid] = -1; s_norm[nxt][tid] = 0.0f;
                }
            }
            int node = (lrow_half < cntN) ? g_src_s[startn + lrow_half] : 0;
            const __nv_bfloat16* ah = g_x_hi + (size_t)node * DDIM + lhalf * 64;
            const __nv_bfloat16* al = g_x_lo + (size_t)node * DDIM + lhalf * 64;
            uint32_t ab = sbase + (nxt ? SM_A1 : SM_A0);
            #pragma unroll
            for (int i = 0; i < 8; ++i) {
                uint32_t off = swz((uint32_t)lrow_half, (uint32_t)(lhalf * 8 + i));
                CP_ASYNC16(ab + off, ah + i * 8);
                CP_ASYNC16(ab + 32768u + off, al + i * 8);
            }
            CP_COMMIT();
            CP_WAIT1();     // tile t's group done; t+1's may remain in flight
        } else {
            CP_WAIT0();
        }

        // ---- (re)load W_r if relation changed ----
        if (r != prev_rel) {
            const uint4* bh = (const uint4*)(g_wt_hi + (size_t)r * DDIM * DDIM + lrow_half * DDIM + lhalf * 64);
            const uint4* bl = (const uint4*)(g_wt_lo + (size_t)r * DDIM * DDIM + lrow_half * DDIM + lhalf * 64);
            #pragma unroll
            for (int i = 0; i < 8; ++i) {
                uint32_t off = swz((uint32_t)lrow_half, (uint32_t)(lhalf * 8 + i));
                *(uint4*)(smem + SM_B_HI + off) = bh[i];
                *(uint4*)(smem + SM_B_LO + off) = bl[i];
            }
            prev_rel = r;
        }
        __syncthreads();   // A[cur] + W visible to all threads

        // ---- MMA mainloop: D = A_hi*B_hi + A_hi*B_lo + A_lo*B_hi ----
        uint32_t abase = sbase + (cur ? SM_A1 : SM_A0);
        int m0 = wid * 16;
        float acc[16][4];
        #pragma unroll
        for (int i = 0; i < 16; ++i)
            #pragma unroll
            for (int j = 0; j < 4; ++j) acc[i][j] = 0.0f;

        uint32_t lr = (uint32_t)(lane & 15);
        uint32_t lc = (uint32_t)(lane >> 4);

        #pragma unroll
        for (int ks = 0; ks < 8; ++ks) {
            uint32_t chunk = (uint32_t)(ks * 2) + lc;
            uint32_t aoff = swz((uint32_t)m0 + lr, chunk);
            uint32_t ah[4], al[4];
            LDMX4(ah, abase + aoff);
            LDMX4(al, abase + 32768u + aoff);
            #pragma unroll
            for (int nt = 0; nt < 16; nt += 2) {
                uint32_t boff = swz((uint32_t)(nt * 8) + lr, chunk);
                uint32_t bh[4], bl[4];
                LDMX4(bh, sbase + SM_B_HI + boff);
                LDMX4(bl, sbase + SM_B_LO + boff);
                MMA_BF16(acc[nt],     ah, bh[0], bh[2]);
                MMA_BF16(acc[nt],     ah, bl[0], bl[2]);
                MMA_BF16(acc[nt],     al, bh[0], bh[2]);
                MMA_BF16(acc[nt + 1], ah, bh[1], bh[3]);
                MMA_BF16(acc[nt + 1], ah, bl[1], bl[3]);
                MMA_BF16(acc[nt + 1], al, bh[1], bh[3]);
            }
        }

        // ---- epilogue: pair lanes via shfl_xor -> red.v4 ----
        {
            int r0 = m0 + (lane >> 2);
            int r1 = r0 + 8;
            int tg0 = s_tgt[cur][r0], tg1 = s_tgt[cur][r1];
            float f0 = s_norm[cur][r0], f1 = s_norm[cur][r1];
            int colb = (lane & 2) << 1;            // 0 or 4
            bool evenl = (lane & 1) == 0;
            int mytgt = evenl ? tg0 : tg1;
            float* hp = g_h + (size_t)(mytgt < 0 ? 0 : mytgt) * DDIM + colb;
            #pragma unroll
            for (int nt = 0; nt < 16; ++nt) {
                float v0 = acc[nt][0] * f0, v1 = acc[nt][1] * f0;
                float v2 = acc[nt][2] * f1, v3 = acc[nt][3] * f1;
                float o0 = __shfl_xor_sync(0xffffffffu, v0, 1);
                float o1 = __shfl_xor_sync(0xffffffffu, v1, 1);
                float o2 = __shfl_xor_sync(0xffffffffu, v2, 1);
                float o3 = __shfl_xor_sync(0xffffffffu, v3, 1);
                float w0, w1, w2, w3;
                if (evenl) { w0 = v0; w1 = v1; w2 = o0; w3 = o1; }
                else       { w0 = o2; w1 = o3; w2 = v2; w3 = v3; }
                if (mytgt >= 0) {
                    asm volatile("red.global.add.v4.f32 [%0], {%1, %2, %3, %4};"
                                 :: "l"(hp + nt * 8), "f"(w0), "f"(w1), "f"(w2), "f"(w3)
                                 : "memory");
                }
            }
        }
        __syncthreads();   // epilogue done before meta[nxt->cur] overwritten / W reload
    }
}

// -------- K8: fused relu + DistMult scoring --------
__global__ void score_kernel(const float* __restrict__ rel_emb, float* __restrict__ out) {
    int gt = blockIdx.x * blockDim.x + threadIdx.x;
    int tri = gt >> 5;
    int lane = gt & 31;
    if (tri >= T_TRIP) return;
    int hn = g_head[tri], tn = g_tail[tri], r = g_ridx[tri];
    const float4 a = *(const float4*)&g_h[(size_t)hn * DDIM + lane * 4];
    const float4 b = *(const float4*)&g_h[(size_t)tn * DDIM + lane * 4];
    const float4 c = *(const float4*)&rel_emb[(size_t)r * DDIM + lane * 4];
    float s = fmaxf(a.x, 0.0f) * c.x * fmaxf(b.x, 0.0f)
            + fmaxf(a.y, 0.0f) * c.y * fmaxf(b.y, 0.0f)
            + fmaxf(a.z, 0.0f) * c.z * fmaxf(b.z, 0.0f)
            + fmaxf(a.w, 0.0f) * c.w * fmaxf(b.w, 0.0f);
    #pragma unroll
    for (int o = 16; o > 0; o >>= 1) s += __shfl_down_sync(0xffffffffu, s, o);
    if (lane == 0) out[tri] = s;
}

// -------- launch --------
extern "C" void kernel_launch(void* const* d_in, const int* in_sizes, int n_in,
                              void* d_out, int out_size) {
    const float* x        = (const float*)d_in[0];
    const float* W        = (const float*)d_in[1];
    const float* Wroot    = (const float*)d_in[2];
    const float* bias     = (const float*)d_in[3];
    const float* rel_emb  = (const float*)d_in[4];
    const void*  edge_idx = d_in[5];
    const void*  edge_typ = d_in[6];
    const void*  head     = d_in[7];
    const void*  tail     = d_in[8];
    const void*  ridx     = d_in[9];
    float* out = (float*)d_out;

    const int SMEM_ROOT = (DDIM * DDIM + DDIM * XP) * (int)sizeof(float);
    cudaFuncSetAttribute(root_gemm_kernel, cudaFuncAttributeMaxDynamicSharedMemorySize, SMEM_ROOT);
    cudaFuncSetAttribute(edge_mma_kernel, cudaFuncAttributeMaxDynamicSharedMemorySize, SMEM_EDGE_BYTES);

    prep_kernel<<<(N_NODES * R_REL + 255) / 256, 256>>>(edge_idx);
    convert_kernel<<<(E_EDGES + 255) / 256, 256>>>(edge_idx, edge_typ, head, tail, ridx);
    scan_kernel<<<1, 32>>>();
    scatter_kernel<<<(E_EDGES + 255) / 256, 256>>>();
    split_kernel<<<(XN + WN + 255) / 256, 256>>>(x, W);
    root_gemm_kernel<<<(N_NODES + 63) / 64, 256, SMEM_ROOT>>>(x, Wroot, bias);
    edge_mma_kernel<<<EDGE_GRID, 256, SMEM_EDGE_BYTES>>>();
    score_kernel<<<(T_TRIP * 32 + 255) / 256, 256>>>(rel_emb, out);
}

// round 5
// speedup vs baseline: 3.8606x; 1.4600x over previous
#include <cuda_runtime.h>
#include <cuda_bf16.h>
#include <cstdint>

// Problem constants (fixed by reference)
#define N_NODES 50000
#define R_REL   32
#define DDIM    128
#define E_EDGES 600000
#define T_TRIP  8192

#define BLK     64                         // edge rows per MMA tile
#define ROOT_TILES ((N_NODES + BLK - 1) / BLK)        // 782
#define MAX_TILES (E_EDGES / BLK + R_REL + ROOT_TILES + 2)
#define EDGE_GRID 296                      // 2 CTAs / SM
#define NB      586                        // scatter blocks (1024 thr each)

// dynamic smem layout for edge kernel (96 KB)
#define SM_B_HI 0
#define SM_B_LO 32768
#define SM_A    65536                      // A hi at +0 (16KB), lo at +16384
#define SMEM_EDGE_BYTES 98304

__device__ __forceinline__ uint32_t smem_to_u32(const void* smem_ptr) {
    uint32_t addr;
    asm("{ .reg .u64 tmp; cvta.to.shared.u64 tmp, %1; cvt.u32.u64 %0, tmp; }"
        : "=r"(addr) : "l"(smem_ptr));
    return addr;
}
// XOR swizzle: row-major [rows][128] bf16, 256B/row, 16 chunks of 16B per row.
__device__ __forceinline__ uint32_t swz(uint32_t row, uint32_t chunk) {
    return row * 256u + ((chunk ^ (row & 7u)) << 4);
}
#define LDMX4(r, addr) \
    asm volatile("ldmatrix.sync.aligned.m8n8.x4.shared.b16 {%0,%1,%2,%3}, [%4];" \
        : "=r"((r)[0]), "=r"((r)[1]), "=r"((r)[2]), "=r"((r)[3]) : "r"(addr))
#define MMA_BF16(d, a, b0, b1) \
    asm volatile("mma.sync.aligned.m16n8k16.row.col.f32.bf16.bf16.f32 " \
        "{%0,%1,%2,%3}, {%4,%5,%6,%7}, {%8,%9}, {%0,%1,%2,%3};" \
        : "+f"((d)[0]), "+f"((d)[1]), "+f"((d)[2]), "+f"((d)[3]) \
        : "r"((a)[0]), "r"((a)[1]), "r"((a)[2]), "r"((a)[3]), "r"(b0), "r"(b1))
#define CP_ASYNC16(dst_u32, gptr) \
    asm volatile("cp.async.cg.shared.global [%0], [%1], 16;" \
        :: "r"(dst_u32), "l"(gptr) : "memory")
#define CP_COMMIT() asm volatile("cp.async.commit_group;" ::: "memory")
#define CP_WAIT0()  asm volatile("cp.async.wait_group 0;" ::: "memory")

// -------- device scratch (static, no allocation) --------
__device__ int   g_is64;
__device__ int   g_cnt[N_NODES * R_REL];
__device__ float g_h[(size_t)N_NODES * DDIM];
__device__ int   g_src[E_EDGES];
__device__ int   g_tgt[E_EDGES];
__device__ int   g_rel[E_EDGES];
__device__ int   g_src_s[E_EDGES];      // relation-sorted
__device__ int   g_tgt_s[E_EDGES];
__device__ float g_norm_s[E_EDGES];
__device__ int   g_head[T_TRIP], g_tail[T_TRIP], g_ridx[T_TRIP];
__device__ int   g_bh[NB * R_REL];      // per-block relation histogram
__device__ int   g_boff[NB * R_REL];    // per-block placement offsets
__device__ int   g_off[R_REL + 1];
__device__ int   g_tile_rel[MAX_TILES];
__device__ int   g_tile_start[MAX_TILES];
__device__ int   g_ntiles;
// bf16 hi/lo splits: 33 relations (slot 32 = W_root)
__device__ __align__(16) __nv_bfloat16 g_x_hi[(size_t)N_NODES * DDIM];
__device__ __align__(16) __nv_bfloat16 g_x_lo[(size_t)N_NODES * DDIM];
__device__ __align__(16) __nv_bfloat16 g_wt_hi[(size_t)(R_REL + 1) * DDIM * DDIM];
__device__ __align__(16) __nv_bfloat16 g_wt_lo[(size_t)(R_REL + 1) * DDIM * DDIM];

__device__ __forceinline__ int ld_idx(const void* p, long long i, int is64) {
    return is64 ? (int)((const long long*)p)[i] : ((const int*)p)[i];
}

// -------- K1: zero counters + dtype detect --------
__global__ void prep_kernel(const void* edge_index) {
    int i = blockIdx.x * blockDim.x + threadIdx.x;
    if (i < N_NODES * R_REL) g_cnt[i] = 0;
    if (blockIdx.x == 0 && threadIdx.x == 0) {
        const unsigned int* p = (const unsigned int*)edge_index;
        int is64 = 1;
        for (int k = 0; k < 64; ++k)
            if (p[2 * k + 1] != 0u) { is64 = 0; break; }
        g_is64 = is64;
    }
}

// -------- K2: convert edges + triplets (int32), per-(node,rel) counts --------
__global__ void convert_kernel(const void* edge_index, const void* edge_type,
                               const void* head, const void* tail, const void* ridx) {
    int i = blockIdx.x * blockDim.x + threadIdx.x;
    int is64 = g_is64;
    if (i < T_TRIP) {
        g_head[i] = ld_idx(head, i, is64);
        g_tail[i] = ld_idx(tail, i, is64);
        g_ridx[i] = ld_idx(ridx, i, is64);
    }
    if (i >= E_EDGES) return;
    int s = ld_idx(edge_index, i, is64);
    int t = ld_idx(edge_index, (long long)E_EDGES + i, is64);
    int r = ld_idx(edge_type, i, is64);
    g_src[i] = s; g_tgt[i] = t; g_rel[i] = r;
    atomicAdd(&g_cnt[t * R_REL + r], 1);
}

// -------- K3: per-block relation histogram (smem atomics) --------
__global__ void blockhist_kernel() {
    __shared__ int cnt[R_REL];
    int tid = threadIdx.x;
    if (tid < R_REL) cnt[tid] = 0;
    __syncthreads();
    int e = blockIdx.x * 1024 + tid;
    if (e < E_EDGES) atomicAdd(&cnt[g_rel[e]], 1);
    __syncthreads();
    if (tid < R_REL) g_bh[blockIdx.x * R_REL + tid] = cnt[tid];
}

// -------- K4: scans (relation offsets, per-block offsets, tile descriptors) --------
__global__ void scan_kernel() {
    __shared__ int relTot[R_REL];
    __shared__ int relOff[R_REL + 1];
    __shared__ int tileOff[R_REL + 1];
    __shared__ int ntE;
    int tid = threadIdx.x;
    if (tid < R_REL) {
        int tot = 0;
        for (int b = 0; b < NB; ++b) tot += g_bh[b * R_REL + tid];
        relTot[tid] = tot;
    }
    __syncthreads();
    if (tid == 0) {
        int acc = 0, tacc = 0;
        for (int r = 0; r < R_REL; ++r) {
            relOff[r] = acc; tileOff[r] = tacc;
            acc += relTot[r];
            tacc += (relTot[r] + BLK - 1) / BLK;
        }
        relOff[R_REL] = acc; tileOff[R_REL] = tacc;
        ntE = tacc;
        g_ntiles = tacc + ROOT_TILES;
        g_off[R_REL] = acc;
    }
    __syncthreads();
    if (tid < R_REL) {
        g_off[tid] = relOff[tid];
        // per-block placement offsets
        int run = relOff[tid];
        for (int b = 0; b < NB; ++b) {
            g_boff[b * R_REL + tid] = run;
            run += g_bh[b * R_REL + tid];
        }
        // edge tile descriptors
        int nt = (relTot[tid] + BLK - 1) / BLK;
        int tb = tileOff[tid];
        for (int i = 0; i < nt; ++i) {
            g_tile_rel[tb + i] = tid;
            g_tile_start[tb + i] = relOff[tid] + i * BLK;
        }
    }
    __syncthreads();
    // root tiles (relation 32, start = node base)
    for (int i = tid; i < ROOT_TILES; i += blockDim.x) {
        g_tile_rel[ntE + i] = R_REL;
        g_tile_start[ntE + i] = i * BLK;
    }
}

// -------- K5: scatter via smem-rank + precomputed block offsets --------
__global__ void scatter_kernel() {
    __shared__ int rank[R_REL];
    __shared__ int base[R_REL];
    int tid = threadIdx.x;
    if (tid < R_REL) {
        rank[tid] = 0;
        base[tid] = g_boff[blockIdx.x * R_REL + tid];
    }
    __syncthreads();
    int e = blockIdx.x * 1024 + tid;
    if (e >= E_EDGES) return;
    int r = g_rel[e];
    int k = atomicAdd(&rank[r], 1);
    int pos = base[r] + k;
    int t = g_tgt[e];
    g_src_s[pos] = g_src[e];
    g_tgt_s[pos] = t;
    g_norm_s[pos] = 1.0f / (float)g_cnt[t * R_REL + r];
}

// -------- K6: bf16 splits of x and W^T (33 relations incl. root) --------
#define XN (N_NODES * DDIM)
#define WN ((R_REL + 1) * DDIM * DDIM)
__global__ void split_kernel(const float* __restrict__ x, const float* __restrict__ W,
                             const float* __restrict__ Wroot) {
    int i = blockIdx.x * blockDim.x + threadIdx.x;
    if (i < XN) {
        float v = x[i];
        __nv_bfloat16 hi = __float2bfloat16(v);
        g_x_hi[i] = hi;
        g_x_lo[i] = __float2bfloat16(v - __bfloat162float(hi));
    }
    int j = i - XN;
    if (j >= 0 && j < WN) {
        int r = j >> 14;
        int o = (j >> 7) & 127;
        int k = j & 127;
        float v = (r < R_REL) ? W[(size_t)r * DDIM * DDIM + (size_t)k * DDIM + o]
                              : Wroot[(size_t)k * DDIM + o];
        __nv_bfloat16 hi = __float2bfloat16(v);
        g_wt_hi[j] = hi;
        g_wt_lo[j] = __float2bfloat16(v - __bfloat162float(hi));
    }
}

// -------- K7: h = bias (broadcast init) --------
__global__ void hinit_kernel(const float* __restrict__ bias) {
    int i = blockIdx.x * blockDim.x + threadIdx.x;
    if (i >= N_NODES * DDIM / 4) return;
    const float4* b4 = (const float4*)bias;
    ((float4*)g_h)[i] = b4[i & 31];
}

// -------- K8: persistent HMMA bf16x3 GEMM (edges + root), 2 CTAs/SM --------
__global__ void __launch_bounds__(256, 2)
edge_mma_kernel() {
    extern __shared__ char smem[];
    __shared__ int   s_tgt[2][BLK];
    __shared__ float s_norm[2][BLK];

    int ntiles = g_ntiles;
    int bid = blockIdx.x;
    int t0 = (int)(((long long)bid * ntiles) / EDGE_GRID);
    int t1 = (int)(((long long)(bid + 1) * ntiles) / EDGE_GRID);
    if (t0 >= t1) return;

    int tid  = threadIdx.x;
    int wid  = tid >> 5;
    int lane = tid & 31;
    uint32_t sbase = smem_to_u32(smem);
    int arow = tid >> 2;        // 0..63 (A gather row)
    int aq   = tid & 3;         // quarter of the 256B row

    // ---- prologue: prefetch tile t0 into buf 0 ----
    {
        int r = g_tile_rel[t0], start = g_tile_start[t0];
        int cnt = (r == R_REL) ? min(BLK, N_NODES - start)
                               : min(BLK, g_off[r + 1] - start);
        if (tid < BLK) {
            if (tid < cnt) {
                if (r == R_REL) { s_tgt[0][tid] = start + tid; s_norm[0][tid] = 1.0f; }
                else { s_tgt[0][tid] = g_tgt_s[start + tid]; s_norm[0][tid] = g_norm_s[start + tid]; }
            } else { s_tgt[0][tid] = -1; s_norm[0][tid] = 0.0f; }
        }
        int nd = 0;
        if (arow < cnt) nd = (r == R_REL) ? (start + arow) : g_src_s[start + arow];
        const __nv_bfloat16* ah = g_x_hi + (size_t)nd * DDIM + aq * 32;
        const __nv_bfloat16* al = g_x_lo + (size_t)nd * DDIM + aq * 32;
        #pragma unroll
        for (int i = 0; i < 4; ++i) {
            uint32_t off = swz((uint32_t)arow, (uint32_t)(aq * 4 + i));
            CP_ASYNC16(sbase + SM_A + off, ah + i * 8);
            CP_ASYNC16(sbase + SM_A + 16384u + off, al + i * 8);
        }
        CP_COMMIT();
    }

    int prev_rel = -1;
    int mq = wid & 3, nq = wid >> 2;
    int m0 = mq * 16, n0 = nq * 64;
    uint32_t lr = (uint32_t)(lane & 15);
    uint32_t lc = (uint32_t)(lane >> 4);

    for (int t = t0; t < t1; ++t) {
        int cur = (t - t0) & 1;
        int r = g_tile_rel[t];

        CP_WAIT0();
        if (r != prev_rel) {
            int brow = tid >> 1, bhalf = tid & 1;
            const uint4* bh = (const uint4*)(g_wt_hi + (size_t)r * DDIM * DDIM + brow * DDIM + bhalf * 64);
            const uint4* bl = (const uint4*)(g_wt_lo + (size_t)r * DDIM * DDIM + brow * DDIM + bhalf * 64);
            #pragma unroll
            for (int i = 0; i < 8; ++i) {
                uint32_t off = swz((uint32_t)brow, (uint32_t)(bhalf * 8 + i));
                *(uint4*)(smem + SM_B_HI + off) = bh[i];
                *(uint4*)(smem + SM_B_LO + off) = bl[i];
            }
            prev_rel = r;
        }
        __syncthreads();   // A + W + meta visible

        // ---- MMA mainloop: D = A_hi*B_hi + A_hi*B_lo + A_lo*B_hi ----
        float acc[8][4];
        #pragma unroll
        for (int i = 0; i < 8; ++i)
            #pragma unroll
            for (int j = 0; j < 4; ++j) acc[i][j] = 0.0f;

        #pragma unroll
        for (int ks = 0; ks < 8; ++ks) {
            uint32_t chunk = (uint32_t)(ks * 2) + lc;
            uint32_t aoff = swz((uint32_t)m0 + lr, chunk);
            uint32_t ah[4], al[4];
            LDMX4(ah, sbase + SM_A + aoff);
            LDMX4(al, sbase + SM_A + 16384u + aoff);
            #pragma unroll
            for (int nt = 0; nt < 8; nt += 2) {
                uint32_t boff = swz((uint32_t)(n0 + nt * 8) + lr, chunk);
                uint32_t bh[4], bl[4];
                LDMX4(bh, sbase + SM_B_HI + boff);
                LDMX4(bl, sbase + SM_B_LO + boff);
                MMA_BF16(acc[nt],     ah, bh[0], bh[2]);
                MMA_BF16(acc[nt],     ah, bl[0], bl[2]);
                MMA_BF16(acc[nt],     al, bh[0], bh[2]);
                MMA_BF16(acc[nt + 1], ah, bh[1], bh[3]);
                MMA_BF16(acc[nt + 1], ah, bl[1], bl[3]);
                MMA_BF16(acc[nt + 1], al, bh[1], bh[3]);
            }
        }
        __syncthreads();   // all warps done reading A

        // ---- prefetch tile t+1 (overlaps epilogue) ----
        if (t + 1 < t1) {
            int nxt = cur ^ 1;
            int rn = g_tile_rel[t + 1], startn = g_tile_start[t + 1];
            int cntn = (rn == R_REL) ? min(BLK, N_NODES - startn)
                                     : min(BLK, g_off[rn + 1] - startn);
            if (tid < BLK) {
                if (tid < cntn) {
                    if (rn == R_REL) { s_tgt[nxt][tid] = startn + tid; s_norm[nxt][tid] = 1.0f; }
                    else { s_tgt[nxt][tid] = g_tgt_s[startn + tid]; s_norm[nxt][tid] = g_norm_s[startn + tid]; }
                } else { s_tgt[nxt][tid] = -1; s_norm[nxt][tid] = 0.0f; }
            }
            int nd = 0;
            if (arow < cntn) nd = (rn == R_REL) ? (startn + arow) : g_src_s[startn + arow];
            const __nv_bfloat16* ah = g_x_hi + (size_t)nd * DDIM + aq * 32;
            const __nv_bfloat16* al = g_x_lo + (size_t)nd * DDIM + aq * 32;
            #pragma unroll
            for (int i = 0; i < 4; ++i) {
                uint32_t off = swz((uint32_t)arow, (uint32_t)(aq * 4 + i));
                CP_ASYNC16(sbase + SM_A + off, ah + i * 8);
                CP_ASYNC16(sbase + SM_A + 16384u + off, al + i * 8);
            }
            CP_COMMIT();
        }

        // ---- epilogue: pair lanes via shfl_xor -> red.v4 ----
        {
            int r0 = m0 + (lane >> 2);
            int r1 = r0 + 8;
            int tg0 = s_tgt[cur][r0], tg1 = s_tgt[cur][r1];
            float f0 = s_norm[cur][r0], f1 = s_norm[cur][r1];
            int colb = (lane & 2) << 1;
            bool evenl = (lane & 1) == 0;
            int mytgt = evenl ? tg0 : tg1;
            float* hp = g_h + (size_t)(mytgt < 0 ? 0 : mytgt) * DDIM + n0 + colb;
            #pragma unroll
            for (int nt = 0; nt < 8; ++nt) {
                float v0 = acc[nt][0] * f0, v1 = acc[nt][1] * f0;
                float v2 = acc[nt][2] * f1, v3 = acc[nt][3] * f1;
                float o0 = __shfl_xor_sync(0xffffffffu, v0, 1);
                float o1 = __shfl_xor_sync(0xffffffffu, v1, 1);
                float o2 = __shfl_xor_sync(0xffffffffu, v2, 1);
                float o3 = __shfl_xor_sync(0xffffffffu, v3, 1);
                float w0, w1, w2, w3;
                if (evenl) { w0 = v0; w1 = v1; w2 = o0; w3 = o1; }
                else       { w0 = o2; w1 = o3; w2 = v2; w3 = v3; }
                if (mytgt >= 0) {
                    asm volatile("red.global.add.v4.f32 [%0], {%1, %2, %3, %4};"
                                 :: "l"(hp + nt * 8), "f"(w0), "f"(w1), "f"(w2), "f"(w3)
                                 : "memory");
                }
            }
        }
        // no tail sync: next iteration's CP_WAIT0 + __syncthreads covers ordering
    }
}

// -------- K9: fused relu + DistMult scoring --------
__global__ void score_kernel(const float* __restrict__ rel_emb, float* __restrict__ out) {
    int gt = blockIdx.x * blockDim.x + threadIdx.x;
    int tri = gt >> 5;
    int lane = gt & 31;
    if (tri >= T_TRIP) return;
    int hn = g_head[tri], tn = g_tail[tri], r = g_ridx[tri];
    const float4 a = *(const float4*)&g_h[(size_t)hn * DDIM + lane * 4];
    const float4 b = *(const float4*)&g_h[(size_t)tn * DDIM + lane * 4];
    const float4 c = *(const float4*)&rel_emb[(size_t)r * DDIM + lane * 4];
    float s = fmaxf(a.x, 0.0f) * c.x * fmaxf(b.x, 0.0f)
            + fmaxf(a.y, 0.0f) * c.y * fmaxf(b.y, 0.0f)
            + fmaxf(a.z, 0.0f) * c.z * fmaxf(b.z, 0.0f)
            + fmaxf(a.w, 0.0f) * c.w * fmaxf(b.w, 0.0f);
    #pragma unroll
    for (int o = 16; o > 0; o >>= 1) s += __shfl_down_sync(0xffffffffu, s, o);
    if (lane == 0) out[tri] = s;
}

// -------- launch --------
extern "C" void kernel_launch(void* const* d_in, const int* in_sizes, int n_in,
                              void* d_out, int out_size) {
    const float* x        = (const float*)d_in[0];
    const float* W        = (const float*)d_in[1];
    const float* Wroot    = (const float*)d_in[2];
    const float* bias     = (const float*)d_in[3];
    const float* rel_emb  = (const float*)d_in[4];
    const void*  edge_idx = d_in[5];
    const void*  edge_typ = d_in[6];
    const void*  head     = d_in[7];
    const void*  tail     = d_in[8];
    const void*  ridx     = d_in[9];
    float* out = (float*)d_out;

    cudaFuncSetAttribute(edge_mma_kernel, cudaFuncAttributeMaxDynamicSharedMemorySize, SMEM_EDGE_BYTES);

    prep_kernel<<<(N_NODES * R_REL + 255) / 256, 256>>>(edge_idx);
    convert_kernel<<<(E_EDGES + 255) / 256, 256>>>(edge_idx, edge_typ, head, tail, ridx);
    blockhist_kernel<<<NB, 1024>>>();
    scan_kernel<<<1, 1024>>>();
    scatter_kernel<<<NB, 1024>>>();
    split_kernel<<<(XN + WN + 255) / 256, 256>>>(x, W, Wroot);
    hinit_kernel<<<(N_NODES * DDIM / 4 + 255) / 256, 256>>>(bias);
    edge_mma_kernel<<<EDGE_GRID, 256, SMEM_EDGE_BYTES>>>();
    score_kernel<<<(T_TRIP * 32 + 255) / 256, 256>>>(rel_emb, out);
}